// round 16
// baseline (speedup 1.0000x reference)
#include <cuda_runtime.h>
#include <cuda_fp16.h>
#include <cstdint>

#define BB 4
#define SS 4096
#define DD 256

// ---------------- static device scratch (no cudaMalloc) ----------------
// Q/K/V stored PRE-SWIZZLED in tile blocks (cp.async.bulk image):
//   Q: 128-row x 512B blocks;  K/V: 64-row x 512B blocks.
__device__ __align__(65536) __half g_Qh[BB * SS * DD];
__device__ __align__(65536) __half g_Kh[BB * SS * DD];
__device__ __align__(65536) __half g_Vh[BB * SS * DD];

// ---------------- helpers ----------------
__device__ __forceinline__ uint32_t smem_u32(const void* p) {
    uint32_t a;
    asm("{ .reg .u64 t; cvta.to.shared.u64 t, %1; cvt.u32.u64 %0, t; }" : "=r"(a) : "l"(p));
    return a;
}
__device__ __forceinline__ uint32_t pack2(float a, float b) {
    __half2 h = __floats2half2_rn(a, b);
    return *reinterpret_cast<uint32_t*>(&h);
}
__device__ __forceinline__ float ex2f(float x) {
    float r; asm("ex2.approx.f32 %0, %1;" : "=f"(r) : "f"(x)); return r;
}
__device__ __forceinline__ uint2 ldcs2(const uint32_t* p) {
    uint2 v;
    asm volatile("ld.global.cs.v2.u32 {%0,%1}, [%2];" : "=r"(v.x), "=r"(v.y) : "l"(p));
    return v;
}
__device__ __forceinline__ void ldsm_x4(uint32_t& r0, uint32_t& r1, uint32_t& r2, uint32_t& r3, uint32_t a) {
    asm volatile("ldmatrix.sync.aligned.m8n8.x4.shared.b16 {%0,%1,%2,%3}, [%4];"
        : "=r"(r0), "=r"(r1), "=r"(r2), "=r"(r3) : "r"(a));
}
__device__ __forceinline__ void ldsm_x4t(uint32_t& r0, uint32_t& r1, uint32_t& r2, uint32_t& r3, uint32_t a) {
    asm volatile("ldmatrix.sync.aligned.m8n8.x4.trans.shared.b16 {%0,%1,%2,%3}, [%4];"
        : "=r"(r0), "=r"(r1), "=r"(r2), "=r"(r3) : "r"(a));
}
__device__ __forceinline__ void mma16(float* c,
    uint32_t a0, uint32_t a1, uint32_t a2, uint32_t a3, uint32_t b0, uint32_t b1)
{
    asm volatile("mma.sync.aligned.m16n8k16.row.col.f32.f16.f16.f32 "
        "{%0,%1,%2,%3}, {%4,%5,%6,%7}, {%8,%9}, {%0,%1,%2,%3};"
        : "+f"(c[0]), "+f"(c[1]), "+f"(c[2]), "+f"(c[3])
        : "r"(a0), "r"(a1), "r"(a2), "r"(a3), "r"(b0), "r"(b1));
}
// Bulk async copies (global <-> shared::cta).
__device__ __forceinline__ void bulk_g2s(uint32_t dst, const void* src, uint32_t bytes, uint32_t mbar) {
    asm volatile("cp.async.bulk.shared::cta.global.mbarrier::complete_tx::bytes [%0], [%1], %2, [%3];"
        :: "r"(dst), "l"(src), "r"(bytes), "r"(mbar) : "memory");
}
__device__ __forceinline__ void bulk_s2g(void* dst, uint32_t src, uint32_t bytes) {
    asm volatile("cp.async.bulk.global.shared::cta.bulk_group [%0], [%1], %2;"
        :: "l"(dst), "r"(src), "r"(bytes) : "memory");
}
#define BULK_S2G_COMMIT() asm volatile("cp.async.bulk.commit_group;" ::: "memory")
#define BULK_S2G_WAIT0()  asm volatile("cp.async.bulk.wait_group 0;" ::: "memory")
#define FENCE_ASYNC()     asm volatile("fence.proxy.async.shared::cta;" ::: "memory")
#define MBAR_INIT(mb, c) asm volatile("mbarrier.init.shared.b64 [%0], %1;" :: "r"(mb), "r"(c) : "memory")
#define MBAR_EXPECT(mb, bytes) asm volatile("mbarrier.arrive.expect_tx.shared.b64 _, [%0], %1;" :: "r"(mb), "r"(bytes) : "memory")
#define MBAR_ARRIVE(mb) asm volatile("mbarrier.arrive.shared.b64 _, [%0];" :: "r"(mb) : "memory")
#define MBAR_WAIT(mb, parity) do {                                              \
    uint32_t _mb = (mb); uint32_t _ph = (parity); uint32_t _done;               \
    asm volatile("{\n\t.reg .pred p;\n\t"                                       \
        "mbarrier.try_wait.parity.acquire.cta.shared::cta.b64 p, [%1], %2;\n\t" \
        "selp.b32 %0, 1, 0, p;\n\t}" : "=r"(_done) : "r"(_mb), "r"(_ph) : "memory"); \
    if (!_done) {                                                               \
        asm volatile("{\n\t.reg .pred P1;\n\t"                                  \
            "WL_%=:\n\t"                                                        \
            "mbarrier.try_wait.parity.acquire.cta.shared::cta.b64 P1, [%0], %1, 0x989680;\n\t" \
            "@P1 bra.uni WD_%=;\n\tbra.uni WL_%=;\n\tWD_%=:\n\t}"               \
            :: "r"(_mb), "r"(_ph) : "memory");                                  \
    }                                                                           \
} while (0)
#define SLAB_BAR(id) asm volatile("bar.sync %0, 128;" :: "r"(id) : "memory")

// exp(s/64) = 2^(s * log2(e)/64)
#define EXP_C 0.022542120f

// ---------------- fused projection: {Q,K,V} = fp16(X @ W^T + b) (unchanged) ----------------
__global__ __launch_bounds__(512, 1) void proj_mma_kernel(
    const float* __restrict__ X,
    const float* __restrict__ Wq, const float* __restrict__ bq,
    const float* __restrict__ Wk, const float* __restrict__ bk,
    const float* __restrict__ Wv, const float* __restrict__ bv)
{
    extern __shared__ char sm[];
    uint4* Xs = reinterpret_cast<uint4*>(sm);
    uint4* Ws = reinterpret_cast<uint4*>(sm + 65536);
    const uint32_t sb = smem_u32(sm);
    const uint32_t XB = sb, WB = sb + 65536;

    const int tid = threadIdx.x;
    const int wid = tid >> 5, lane = tid & 31;
    const int lx = lane & 3, ly = lane >> 2;
    const int rs = (wid & 7) * 16;
    const int h  = wid >> 3;
    const int m0 = blockIdx.x * 128;

    const float4* Xg = reinterpret_cast<const float4*>(X);

    #pragma unroll
    for (int p = 0; p < 8; p++) {
        int v = tid + p * 512;
        int row = v >> 5, c = v & 31;
        float4 f0 = Xg[(size_t)(m0 + row) * 64 + c * 2];
        float4 f1 = Xg[(size_t)(m0 + row) * 64 + c * 2 + 1];
        uint4 u = { pack2(f0.x, f0.y), pack2(f0.z, f0.w), pack2(f1.x, f1.y), pack2(f1.z, f1.w) };
        Xs[row * 32 + (c ^ (row & 7))] = u;
    }

    const int rowA = rs + (lane & 15);
    const int ra7  = rowA & 7;
    const uint32_t xrow = XB + rowA * 512;
    const int rl0 = rs + ly, rl1 = rl0 + 8;

    for (int mtx = 0; mtx < 3; mtx++) {
        const float* W; const float* bias; char* Yb;
        if (mtx == 0)      { W = Wq; bias = bq; Yb = (char*)g_Qh; }
        else if (mtx == 1) { W = Wk; bias = bk; Yb = (char*)g_Kh; }
        else               { W = Wv; bias = bv; Yb = (char*)g_Vh; }

        __syncthreads();
        const float4* Wg = reinterpret_cast<const float4*>(W);
        #pragma unroll
        for (int p = 0; p < 16; p++) {
            int v = tid + p * 512;
            int row = v >> 5, c = v & 31;
            float4 f0 = Wg[(size_t)row * 64 + c * 2];
            float4 f1 = Wg[(size_t)row * 64 + c * 2 + 1];
            uint4 u = { pack2(f0.x, f0.y), pack2(f0.z, f0.w), pack2(f1.x, f1.y), pack2(f1.z, f1.w) };
            Ws[row * 32 + (c ^ (row & 7))] = u;
        }
        __syncthreads();

        float C[16][4];
        #pragma unroll
        for (int n = 0; n < 16; n++)
            #pragma unroll
            for (int j = 0; j < 4; j++) C[n][j] = 0.0f;

        #pragma unroll
        for (int kk = 0; kk < 16; kk++) {
            uint32_t a0, a1, a2, a3;
            ldsm_x4(a0, a1, a2, a3, xrow + ((2 * kk + (lane >> 4)) ^ ra7) * 16);
            #pragma unroll
            for (int nn = 0; nn < 16; nn += 2) {
                int n = h * 128 + nn * 8 + ((lane >> 4) & 1) * 8 + (lane & 7);
                uint32_t b0, b1, b2, b3;
                ldsm_x4(b0, b1, b2, b3,
                        WB + n * 512 + ((2 * kk + ((lane >> 3) & 1)) ^ (lane & 7)) * 16);
                mma16(C[nn],     a0, a1, a2, a3, b0, b1);
                mma16(C[nn + 1], a0, a1, a2, a3, b2, b3);
            }
        }

        __syncthreads();

        #pragma unroll
        for (int nn = 0; nn < 16; nn++) {
            const int col = h * 128 + nn * 8 + 2 * lx;
            const int c = col >> 3;
            float2 bi = *reinterpret_cast<const float2*>(bias + col);
            uint32_t v0 = pack2(C[nn][0] + bi.x, C[nn][1] + bi.y);
            uint32_t v1 = pack2(C[nn][2] + bi.x, C[nn][3] + bi.y);
            *reinterpret_cast<uint32_t*>(sm + 65536 + rl0 * 512 + ((c ^ (rl0 & 7)) * 16 + 4 * lx)) = v0;
            *reinterpret_cast<uint32_t*>(sm + 65536 + rl1 * 512 + ((c ^ (rl1 & 7)) * 16 + 4 * lx)) = v1;
        }
        __syncthreads();

        if (tid == 0) {
            FENCE_ASYNC();
            bulk_s2g(Yb + (size_t)m0 * 512, WB, 65536u);
            BULK_S2G_COMMIT();
            BULK_S2G_WAIT0();
        }
    }
}

// ---------------- flash attention: 16 warps = 4 slabs(32 rows) x 4 quarters ----------------
// SMEM: Q 64K @0, K0/K1 @64K/96K, V0/V1 @128K/160K, P 16K @192K, lred 2K @208K, mbars after.
#define K_OFF 65536
#define V_OFF 131072
#define P_OFF 196608
#define L_OFF 212992
#define B_OFF 215040
#define NT (SS / 64)

__global__ __launch_bounds__(512, 1) void attn_mma_kernel(
    float* __restrict__ out, const void* __restrict__ mask_raw)
{
    extern __shared__ char sm[];
    float* lred = reinterpret_cast<float*>(sm + L_OFF);
    const uint32_t sb = smem_u32(sm);
    const uint32_t QB = sb, PB = sb + P_OFF;
    const uint32_t bm = sb + B_OFF;

    const int tid = threadIdx.x;
    const int wid = tid >> 5, lane = tid & 31;
    const int lx = lane & 3, ly = lane >> 2;
    const int slab = wid & 3;          // 4 slabs x 32 rows
    const int rs = slab * 32;
    const int qd = wid >> 2;           // key quarter (QK) / d quarter (PV)
    const int b  = blockIdx.y;
    const int q0 = blockIdx.x * 128;

    const int R0 = rs + ly, R1 = R0 + 8, R2 = R0 + 16, R3 = R0 + 24;

    const char* Ksrc = (const char*)g_Kh + ((size_t)b * 64) * 32768;
    const char* Vsrc = (const char*)g_Vh + ((size_t)b * 64) * 32768;
    const char* Qsrc = (const char*)g_Qh + ((size_t)(b * 32 + blockIdx.x)) * 65536;
    // single base pointer for mask rows (row f = base + f*8*SS elements)
    const uint32_t* Mwb = reinterpret_cast<const uint32_t*>(mask_raw) + (size_t)(b * SS + q0 + R0) * SS;
    const uint8_t*  Mbb = reinterpret_cast<const uint8_t*>(mask_raw) + (size_t)(b * SS + q0 + R0) * SS;

    // ---- inline mask layout detection ----
    int bad = 0;
    if (tid < 256) {
        uint32_t w = reinterpret_cast<const uint32_t*>(mask_raw)[tid];
        bad = (w != 0u && w != 1u && w != 0x3F800000u) ? 1 : 0;
    }
    const int layout = __syncthreads_or(bad);   // 1 = packed bytes, 0 = word per element

    // init mbarriers, then launch Q bulk + tiles 0 and 1
    if (tid == 0) {
        MBAR_INIT(bm + 0, 1);
        MBAR_INIT(bm + 8, 1);
        MBAR_INIT(bm + 16, 1);
        MBAR_INIT(bm + 24, 512);
        MBAR_INIT(bm + 32, 512);
    }
    __syncthreads();
    if (tid == 0) {
        MBAR_EXPECT(bm + 16, 65536u);
        bulk_g2s(QB, Qsrc, 65536u, bm + 16);
        MBAR_EXPECT(bm + 0, 65536u);
        bulk_g2s(sb + K_OFF, Ksrc, 32768u, bm + 0);
        bulk_g2s(sb + V_OFF, Vsrc, 32768u, bm + 0);
        MBAR_EXPECT(bm + 8, 65536u);
        bulk_g2s(sb + K_OFF + 32768, Ksrc + 32768, 32768u, bm + 8);
        bulk_g2s(sb + V_OFF + 32768, Vsrc + 32768, 32768u, bm + 8);
    }

    // mask bits: bit (nn*8 + f*2 + j) = ntile nn (of warp's 16 keys), row-frag f, col 2lx+j
    auto load_mask_bits = [&](int t) -> uint32_t {
        uint32_t bits = 0;
        const int colb = t * 64 + qd * 16 + 2 * lx;
        if (layout == 0) {
            #pragma unroll
            for (int nn = 0; nn < 2; nn++)
                #pragma unroll
                for (int f = 0; f < 4; f++) {
                    uint2 v = ldcs2(Mwb + (size_t)f * 8 * SS + colb + nn * 8);
                    if (v.x) bits |= 1u << (nn * 8 + f * 2);
                    if (v.y) bits |= 1u << (nn * 8 + f * 2 + 1);
                }
        } else {
            #pragma unroll
            for (int nn = 0; nn < 2; nn++)
                #pragma unroll
                for (int f = 0; f < 4; f++) {
                    uint32_t v = *reinterpret_cast<const uint16_t*>(Mbb + (size_t)f * 8 * SS + colb + nn * 8);
                    if (v & 0x00ffu) bits |= 1u << (nn * 8 + f * 2);
                    if (v & 0xff00u) bits |= 1u << (nn * 8 + f * 2 + 1);
                }
        }
        return bits;
    };

    float C[16][4];      // C[nn*2+m]: 8 n-tiles (d-quarter) x 2 m-tiles
    #pragma unroll
    for (int n = 0; n < 16; n++)
        #pragma unroll
        for (int j = 0; j < 4; j++) C[n][j] = 0.0f;
    float l[4] = {0.0f, 0.0f, 0.0f, 0.0f};

    const int rowA0 = rs + (lane & 15);
    const int rowA1 = rowA0 + 16;
    const int ra7   = rowA0 & 7;
    const uint32_t qrow0 = QB + rowA0 * 512;
    const uint32_t qrow1 = QB + rowA1 * 512;
    const uint32_t prow0 = PB + rowA0 * 128;
    const uint32_t prow1 = PB + rowA1 * 128;

    uint32_t mbits = load_mask_bits(0);
    MBAR_WAIT(bm + 16, 0);   // Q resident

    for (int t = 0; t < NT; t++) {
        const int buf = t & 1;
        const int ph  = (t >> 1) & 1;
        MBAR_WAIT(bm + buf * 8, ph);   // tile t K+V resident (per-warp)

        const uint32_t KBc = sb + K_OFF + buf * 32768;
        const uint32_t VBc = sb + V_OFF + buf * 32768;

        // ---- QK^T: S[32 rows x 16 keys (quarter qd)] per warp ----
        float S[4][4];                 // S[nn*2+m], nn in {0,1}
        #pragma unroll
        for (int n = 0; n < 4; n++)
            #pragma unroll
            for (int j = 0; j < 4; j++) S[n][j] = 0.0f;

        {
            const int key = qd * 16 + ((lane >> 4) & 1) * 8 + (lane & 7);
            const uint32_t krow = KBc + key * 512;
            const int k7b = lane & 7;
            #pragma unroll
            for (int kk = 0; kk < 16; kk++) {
                uint32_t a0, a1, a2, a3, a4, a5, a6, a7;
                ldsm_x4(a0, a1, a2, a3, qrow0 + ((2 * kk + (lane >> 4)) ^ ra7) * 16);
                ldsm_x4(a4, a5, a6, a7, qrow1 + ((2 * kk + (lane >> 4)) ^ ra7) * 16);
                uint32_t b0, b1, b2, b3;
                ldsm_x4(b0, b1, b2, b3, krow + ((2 * kk + ((lane >> 3) & 1)) ^ k7b) * 16);
                mma16(S[0], a0, a1, a2, a3, b0, b1);
                mma16(S[1], a4, a5, a6, a7, b0, b1);
                mma16(S[2], a0, a1, a2, a3, b2, b3);
                mma16(S[3], a4, a5, a6, a7, b2, b3);
            }
        }

        // ---- softmax: P fragments into regs + smem ----
        uint32_t pp[2][4];   // pp[nn][m*2 + rowhalf]
        #pragma unroll
        for (int nn = 0; nn < 2; nn++)
            #pragma unroll
            for (int m = 0; m < 2; m++) {
                float e0 = ex2f(S[nn * 2 + m][0] * EXP_C);
                float e1 = ex2f(S[nn * 2 + m][1] * EXP_C);
                float e2 = ex2f(S[nn * 2 + m][2] * EXP_C);
                float e3 = ex2f(S[nn * 2 + m][3] * EXP_C);
                e0 = (mbits >> (nn * 8 + (2 * m) * 2))     & 1u ? 0.0f : e0;
                e1 = (mbits >> (nn * 8 + (2 * m) * 2 + 1)) & 1u ? 0.0f : e1;
                e2 = (mbits >> (nn * 8 + (2 * m + 1) * 2))     & 1u ? 0.0f : e2;
                e3 = (mbits >> (nn * 8 + (2 * m + 1) * 2 + 1)) & 1u ? 0.0f : e3;
                l[2 * m]     += e0 + e1;
                l[2 * m + 1] += e2 + e3;
                pp[nn][2 * m]     = pack2(e0, e1);
                pp[nn][2 * m + 1] = pack2(e2, e3);
                const int cc = qd * 2 + nn;
                const int rA = rs + m * 16 + ly, rB = rA + 8;
                *reinterpret_cast<uint32_t*>(sm + P_OFF + rA * 128 + ((cc ^ (rA & 7)) * 16 + 4 * lx)) = pp[nn][2 * m];
                *reinterpret_cast<uint32_t*>(sm + P_OFF + rB * 128 + ((cc ^ (rB & 7)) * 16 + 4 * lx)) = pp[nn][2 * m + 1];
            }

        // ---- prefetch mask(t+1) ----
        if (t + 1 < NT) mbits = load_mask_bits(t + 1);

        // ---- PV own key chunk (kc == qd): A fragments from registers ----
        {
            const int key = qd * 16 + (lane & 7) + ((lane >> 3) & 1) * 8;
            const uint32_t vrow = VBc + key * 512;
            const int k7 = key & 7;
            uint32_t a00 = pp[0][0], a01 = pp[0][1], a02 = pp[1][0], a03 = pp[1][1];
            uint32_t a10 = pp[0][2], a11 = pp[0][3], a12 = pp[1][2], a13 = pp[1][3];
            #pragma unroll
            for (int nn = 0; nn < 8; nn += 2) {
                uint32_t b0, b1, b2, b3;
                ldsm_x4t(b0, b1, b2, b3, vrow + ((qd * 8 + nn + ((lane >> 4) & 1)) ^ k7) * 16);
                mma16(C[nn * 2 + 0],       a00, a01, a02, a03, b0, b1);
                mma16(C[nn * 2 + 1],       a10, a11, a12, a13, b0, b1);
                mma16(C[(nn + 1) * 2 + 0], a00, a01, a02, a03, b2, b3);
                mma16(C[(nn + 1) * 2 + 1], a10, a11, a12, a13, b2, b3);
            }
        }

        SLAB_BAR(slab + 1);   // slab group's P fragments (all 4 quarters) visible

        // ---- PV other 3 key chunks: A fragments from SMEM ----
        #pragma unroll
        for (int kd = 1; kd < 4; kd++) {
            const int kc = (qd + kd) & 3;
            const int key = kc * 16 + (lane & 7) + ((lane >> 3) & 1) * 8;
            const uint32_t vrow = VBc + key * 512;
            const int k7 = key & 7;
            uint32_t a00, a01, a02, a03, a10, a11, a12, a13;
            ldsm_x4(a00, a01, a02, a03, prow0 + ((2 * kc + (lane >> 4)) ^ ra7) * 16);
            ldsm_x4(a10, a11, a12, a13, prow1 + ((2 * kc + (lane >> 4)) ^ ra7) * 16);
            #pragma unroll
            for (int nn = 0; nn < 8; nn += 2) {
                uint32_t b0, b1, b2, b3;
                ldsm_x4t(b0, b1, b2, b3, vrow + ((qd * 8 + nn + ((lane >> 4) & 1)) ^ k7) * 16);
                mma16(C[nn * 2 + 0],       a00, a01, a02, a03, b0, b1);
                mma16(C[nn * 2 + 1],       a10, a11, a12, a13, b0, b1);
                mma16(C[(nn + 1) * 2 + 0], a00, a01, a02, a03, b2, b3);
                mma16(C[(nn + 1) * 2 + 1], a10, a11, a12, a13, b2, b3);
            }
        }

        SLAB_BAR(slab + 1);   // slab group done reading P (before next softmax writes)

        // ---- consumer arrive ----
        MBAR_ARRIVE(bm + 24 + buf * 8);

        // ---- thread0: refill buffer for t+2 once fully consumed ----
        if (tid == 0 && t + 2 < NT) {
            MBAR_WAIT(bm + 24 + buf * 8, ph);
            const uint32_t db = bm + buf * 8;
            MBAR_EXPECT(db, 65536u);
            bulk_g2s(sb + K_OFF + buf * 32768, Ksrc + (size_t)(t + 2) * 32768, 32768u, db);
            bulk_g2s(sb + V_OFF + buf * 32768, Vsrc + (size_t)(t + 2) * 32768, 32768u, db);
        }
    }

    // ---- epilogue: denominators (quad reduce + 4-quarter sum), normalize, store ----
    #pragma unroll
    for (int f = 0; f < 4; f++) {
        l[f] += __shfl_xor_sync(0xffffffffu, l[f], 1);
        l[f] += __shfl_xor_sync(0xffffffffu, l[f], 2);
    }
    if (lx == 0) {
        lred[R0 * 4 + qd] = l[0];
        lred[R1 * 4 + qd] = l[1];
        lred[R2 * 4 + qd] = l[2];
        lred[R3 * 4 + qd] = l[3];
    }
    __syncthreads();
    float inv[4];
    inv[0] = 1.0f / (lred[R0 * 4] + lred[R0 * 4 + 1] + lred[R0 * 4 + 2] + lred[R0 * 4 + 3]);
    inv[1] = 1.0f / (lred[R1 * 4] + lred[R1 * 4 + 1] + lred[R1 * 4 + 2] + lred[R1 * 4 + 3]);
    inv[2] = 1.0f / (lred[R2 * 4] + lred[R2 * 4 + 1] + lred[R2 * 4 + 2] + lred[R2 * 4 + 3]);
    inv[3] = 1.0f / (lred[R3 * 4] + lred[R3 * 4 + 1] + lred[R3 * 4 + 2] + lred[R3 * 4 + 3]);

    #pragma unroll
    for (int nn = 0; nn < 8; nn++)
        #pragma unroll
        for (int m = 0; m < 2; m++) {
            const int col = qd * 64 + nn * 8 + 2 * lx;
            const int rA = rs + m * 16 + ly, rB = rA + 8;
            float2 o0 = { C[nn * 2 + m][0] * inv[2 * m],     C[nn * 2 + m][1] * inv[2 * m] };
            float2 o1 = { C[nn * 2 + m][2] * inv[2 * m + 1], C[nn * 2 + m][3] * inv[2 * m + 1] };
            *reinterpret_cast<float2*>(out + (size_t)(b * SS + q0 + rA) * DD + col) = o0;
            *reinterpret_cast<float2*>(out + (size_t)(b * SS + q0 + rB) * DD + col) = o1;
        }
}

// ---------------------------------------------------------------------------
extern "C" void kernel_launch(void* const* d_in, const int* in_sizes, int n_in,
                              void* d_out, int out_size)
{
    const float*    X    = (const float*)d_in[0];
    const uint32_t* mask = (const uint32_t*)d_in[1];
    const float*    Wq   = (const float*)d_in[2];
    const float*    bq   = (const float*)d_in[3];
    const float*    Wk   = (const float*)d_in[4];
    const float*    bk   = (const float*)d_in[5];
    const float*    Wv   = (const float*)d_in[6];
    const float*    bv   = (const float*)d_in[7];
    float*          out  = (float*)d_out;

    const int proj_smem = 65536 + 131072;   // 192KB
    cudaFuncSetAttribute(proj_mma_kernel, cudaFuncAttributeMaxDynamicSharedMemorySize, proj_smem);
    proj_mma_kernel<<<128, 512, proj_smem>>>(X, Wq, bq, Wk, bk, Wv, bv);

    const int attn_smem = 215040 + 64;      // Q64K+KV128K+P16K+lred2K+mbars
    cudaFuncSetAttribute(attn_mma_kernel, cudaFuncAttributeMaxDynamicSharedMemorySize, attn_smem);
    attn_mma_kernel<<<dim3(SS / 128, BB), 512, attn_smem>>>(out, (const void*)mask);
}

// round 17
// speedup vs baseline: 1.0643x; 1.0643x over previous
#include <cuda_runtime.h>
#include <cuda_fp16.h>
#include <cstdint>

#define BB 4
#define SS 4096
#define DD 256

// ---------------- static device scratch (no cudaMalloc) ----------------
// All tensors stored PRE-SWIZZLED fp16 images (cp.async.bulk <-> ldmatrix layout):
//   X/Q: 128-row x 512B blocks;  K/V: 64-row x 512B blocks;  W: 256-row x 512B (one block).
__device__ __align__(65536) __half g_Xh[BB * SS * DD];
__device__ __align__(65536) __half g_Qh[BB * SS * DD];
__device__ __align__(65536) __half g_Kh[BB * SS * DD];
__device__ __align__(65536) __half g_Vh[BB * SS * DD];
__device__ __align__(65536) __half g_Wh[3 * DD * DD];

// ---------------- helpers ----------------
__device__ __forceinline__ uint32_t smem_u32(const void* p) {
    uint32_t a;
    asm("{ .reg .u64 t; cvta.to.shared.u64 t, %1; cvt.u32.u64 %0, t; }" : "=r"(a) : "l"(p));
    return a;
}
__device__ __forceinline__ uint32_t pack2(float a, float b) {
    __half2 h = __floats2half2_rn(a, b);
    return *reinterpret_cast<uint32_t*>(&h);
}
__device__ __forceinline__ float ex2f(float x) {
    float r; asm("ex2.approx.f32 %0, %1;" : "=f"(r) : "f"(x)); return r;
}
__device__ __forceinline__ uint2 ldcs2(const uint32_t* p) {
    uint2 v;
    asm volatile("ld.global.cs.v2.u32 {%0,%1}, [%2];" : "=r"(v.x), "=r"(v.y) : "l"(p));
    return v;
}
__device__ __forceinline__ void ldsm_x4(uint32_t& r0, uint32_t& r1, uint32_t& r2, uint32_t& r3, uint32_t a) {
    asm volatile("ldmatrix.sync.aligned.m8n8.x4.shared.b16 {%0,%1,%2,%3}, [%4];"
        : "=r"(r0), "=r"(r1), "=r"(r2), "=r"(r3) : "r"(a));
}
__device__ __forceinline__ void ldsm_x4t(uint32_t& r0, uint32_t& r1, uint32_t& r2, uint32_t& r3, uint32_t a) {
    asm volatile("ldmatrix.sync.aligned.m8n8.x4.trans.shared.b16 {%0,%1,%2,%3}, [%4];"
        : "=r"(r0), "=r"(r1), "=r"(r2), "=r"(r3) : "r"(a));
}
__device__ __forceinline__ void mma16(float* c,
    uint32_t a0, uint32_t a1, uint32_t a2, uint32_t a3, uint32_t b0, uint32_t b1)
{
    asm volatile("mma.sync.aligned.m16n8k16.row.col.f32.f16.f16.f32 "
        "{%0,%1,%2,%3}, {%4,%5,%6,%7}, {%8,%9}, {%0,%1,%2,%3};"
        : "+f"(c[0]), "+f"(c[1]), "+f"(c[2]), "+f"(c[3])
        : "r"(a0), "r"(a1), "r"(a2), "r"(a3), "r"(b0), "r"(b1));
}
// Bulk async copies (global <-> shared::cta).
__device__ __forceinline__ void bulk_g2s(uint32_t dst, const void* src, uint32_t bytes, uint32_t mbar) {
    asm volatile("cp.async.bulk.shared::cta.global.mbarrier::complete_tx::bytes [%0], [%1], %2, [%3];"
        :: "r"(dst), "l"(src), "r"(bytes), "r"(mbar) : "memory");
}
__device__ __forceinline__ void bulk_s2g(void* dst, uint32_t src, uint32_t bytes) {
    asm volatile("cp.async.bulk.global.shared::cta.bulk_group [%0], [%1], %2;"
        :: "l"(dst), "r"(src), "r"(bytes) : "memory");
}
#define BULK_S2G_COMMIT() asm volatile("cp.async.bulk.commit_group;" ::: "memory")
#define BULK_S2G_WAIT0()  asm volatile("cp.async.bulk.wait_group 0;" ::: "memory")
#define FENCE_ASYNC()     asm volatile("fence.proxy.async.shared::cta;" ::: "memory")
#define MBAR_INIT(mb, c) asm volatile("mbarrier.init.shared.b64 [%0], %1;" :: "r"(mb), "r"(c) : "memory")
#define MBAR_EXPECT(mb, bytes) asm volatile("mbarrier.arrive.expect_tx.shared.b64 _, [%0], %1;" :: "r"(mb), "r"(bytes) : "memory")
#define MBAR_ARRIVE(mb) asm volatile("mbarrier.arrive.shared.b64 _, [%0];" :: "r"(mb) : "memory")
#define MBAR_WAIT(mb, parity) do {                                              \
    uint32_t _mb = (mb); uint32_t _ph = (parity); uint32_t _done;               \
    asm volatile("{\n\t.reg .pred p;\n\t"                                       \
        "mbarrier.try_wait.parity.acquire.cta.shared::cta.b64 p, [%1], %2;\n\t" \
        "selp.b32 %0, 1, 0, p;\n\t}" : "=r"(_done) : "r"(_mb), "r"(_ph) : "memory"); \
    if (!_done) {                                                               \
        asm volatile("{\n\t.reg .pred P1;\n\t"                                  \
            "WL_%=:\n\t"                                                        \
            "mbarrier.try_wait.parity.acquire.cta.shared::cta.b64 P1, [%0], %1, 0x989680;\n\t" \
            "@P1 bra.uni WD_%=;\n\tbra.uni WL_%=;\n\tWD_%=:\n\t}"               \
            :: "r"(_mb), "r"(_ph) : "memory");                                  \
    }                                                                           \
} while (0)
#define PAIR_BAR(id) asm volatile("bar.sync %0, 64;" :: "r"(id) : "memory")

// exp(s/64) = 2^(s * log2(e)/64)
#define EXP_C 0.022542120f

// ---------------- pre-pass: fp32 -> swizzled fp16 images of X and W ----------------
// X chunks: 16384 rows x 32 chunks = 524288; W chunks: 3 x 256 x 32 = 24576.
__global__ __launch_bounds__(256) void convert_kernel(
    const float* __restrict__ X,
    const float* __restrict__ Wq, const float* __restrict__ Wk, const float* __restrict__ Wv)
{
    const size_t g = (size_t)blockIdx.x * 256 + threadIdx.x;
    if (g < 524288) {
        const size_t m = g >> 5;
        const int c = (int)(g & 31);
        const float4* src = reinterpret_cast<const float4*>(X) + m * 64 + c * 2;
        float4 f0 = src[0], f1 = src[1];
        uint4 u = { pack2(f0.x, f0.y), pack2(f0.z, f0.w), pack2(f1.x, f1.y), pack2(f1.z, f1.w) };
        char* dst = (char*)g_Xh + (m >> 7) * 65536 + (m & 127) * 512 + ((c ^ (int)(m & 7)) * 16);
        *reinterpret_cast<uint4*>(dst) = u;
    } else {
        const size_t w = g - 524288;
        const int mtx = (int)(w >> 13);
        const int rem = (int)(w & 8191);
        const int r = rem >> 5, c = rem & 31;
        const float* W = (mtx == 0) ? Wq : (mtx == 1) ? Wk : Wv;
        const float4* src = reinterpret_cast<const float4*>(W) + r * 64 + c * 2;
        float4 f0 = src[0], f1 = src[1];
        uint4 u = { pack2(f0.x, f0.y), pack2(f0.z, f0.w), pack2(f1.x, f1.y), pack2(f1.z, f1.w) };
        char* dst = (char*)g_Wh + (size_t)mtx * 131072 + r * 512 + ((c ^ (r & 7)) * 16);
        *reinterpret_cast<uint4*>(dst) = u;
    }
}

// ---------------- projection: {Q,K,V} = fp16(X @ W^T + b), all-bulk staging ----------------
// SMEM: Xs 64K @0, Ws 128K @64K, mbars @192K (+0 X, +8 W).
__global__ __launch_bounds__(512, 1) void proj_mma_kernel(
    const float* __restrict__ bq, const float* __restrict__ bk, const float* __restrict__ bv)
{
    extern __shared__ char sm[];
    const uint32_t sb = smem_u32(sm);
    const uint32_t XB = sb, WB = sb + 65536;
    const uint32_t bm = sb + 196608;

    const int tid = threadIdx.x;
    const int wid = tid >> 5, lane = tid & 31;
    const int lx = lane & 3, ly = lane >> 2;
    const int rs = (wid & 7) * 16;
    const int h  = wid >> 3;
    const int m0 = blockIdx.x * 128;

    if (tid == 0) {
        MBAR_INIT(bm + 0, 1);
        MBAR_INIT(bm + 8, 1);
    }
    __syncthreads();
    if (tid == 0) {
        MBAR_EXPECT(bm + 0, 65536u);
        bulk_g2s(XB, (char*)g_Xh + (size_t)blockIdx.x * 65536, 65536u, bm + 0);
        MBAR_EXPECT(bm + 8, 131072u);
        bulk_g2s(WB, (char*)g_Wh, 131072u, bm + 8);
    }

    const int rowA = rs + (lane & 15);
    const int ra7  = rowA & 7;
    const uint32_t xrow = XB + rowA * 512;
    const int rl0 = rs + ly, rl1 = rl0 + 8;

    MBAR_WAIT(bm + 0, 0);   // X resident

    for (int mtx = 0; mtx < 3; mtx++) {
        const float* bias; char* Yb;
        if (mtx == 0)      { bias = bq; Yb = (char*)g_Qh; }
        else if (mtx == 1) { bias = bk; Yb = (char*)g_Kh; }
        else               { bias = bv; Yb = (char*)g_Vh; }

        MBAR_WAIT(bm + 8, mtx & 1);   // W(mtx) resident

        float C[16][4];
        #pragma unroll
        for (int n = 0; n < 16; n++)
            #pragma unroll
            for (int j = 0; j < 4; j++) C[n][j] = 0.0f;

        #pragma unroll
        for (int kk = 0; kk < 16; kk++) {
            uint32_t a0, a1, a2, a3;
            ldsm_x4(a0, a1, a2, a3, xrow + ((2 * kk + (lane >> 4)) ^ ra7) * 16);
            #pragma unroll
            for (int nn = 0; nn < 16; nn += 2) {
                int n = h * 128 + nn * 8 + ((lane >> 4) & 1) * 8 + (lane & 7);
                uint32_t b0, b1, b2, b3;
                ldsm_x4(b0, b1, b2, b3,
                        WB + n * 512 + ((2 * kk + ((lane >> 3) & 1)) ^ (lane & 7)) * 16);
                mma16(C[nn],     a0, a1, a2, a3, b0, b1);
                mma16(C[nn + 1], a0, a1, a2, a3, b2, b3);
            }
        }

        __syncthreads();   // all mma reads of Ws done before output staging overwrites

        // stage output rows (swizzled gmem image) over Ws
        #pragma unroll
        for (int nn = 0; nn < 16; nn++) {
            const int col = h * 128 + nn * 8 + 2 * lx;
            const int c = col >> 3;
            float2 bi = *reinterpret_cast<const float2*>(bias + col);
            uint32_t v0 = pack2(C[nn][0] + bi.x, C[nn][1] + bi.y);
            uint32_t v1 = pack2(C[nn][2] + bi.x, C[nn][3] + bi.y);
            *reinterpret_cast<uint32_t*>(sm + 65536 + rl0 * 512 + ((c ^ (rl0 & 7)) * 16 + 4 * lx)) = v0;
            *reinterpret_cast<uint32_t*>(sm + 65536 + rl1 * 512 + ((c ^ (rl1 & 7)) * 16 + 4 * lx)) = v1;
        }
        __syncthreads();

        if (tid == 0) {
            FENCE_ASYNC();
            bulk_s2g(Yb + (size_t)m0 * 512, WB, 65536u);
            BULK_S2G_COMMIT();
            BULK_S2G_WAIT0();   // store read of Ws done before next W bulk overwrites
            if (mtx + 1 < 3) {
                MBAR_EXPECT(bm + 8, 131072u);
                bulk_g2s(WB, (char*)g_Wh + (size_t)(mtx + 1) * 131072, 131072u, bm + 8);
            }
        }
    }
}

// ---------------- flash attention: M=32 rows/warp, 256 threads (R15 best, verbatim) ----------
#define K_OFF 65536
#define V_OFF 131072
#define P_OFF 196608
#define L_OFF 212992
#define B_OFF 214016
#define NT (SS / 64)

__global__ __launch_bounds__(256, 1) void attn_mma_kernel(
    float* __restrict__ out, const void* __restrict__ mask_raw)
{
    extern __shared__ char sm[];
    float* lred = reinterpret_cast<float*>(sm + L_OFF);
    const uint32_t sb = smem_u32(sm);
    const uint32_t QB = sb, PB = sb + P_OFF;
    const uint32_t bm = sb + B_OFF;

    const int tid = threadIdx.x;
    const int wid = tid >> 5, lane = tid & 31;
    const int lx = lane & 3, ly = lane >> 2;
    const int slab = wid & 3;          // 4 slabs x 32 rows
    const int rs = slab * 32;
    const int h  = wid >> 2;           // key half (QK) / d half (PV)
    const int b  = blockIdx.y;
    const int q0 = blockIdx.x * 128;

    const int R0 = rs + ly, R1 = R0 + 8, R2 = R0 + 16, R3 = R0 + 24;

    const char* Ksrc = (const char*)g_Kh + ((size_t)b * 64) * 32768;
    const char* Vsrc = (const char*)g_Vh + ((size_t)b * 64) * 32768;
    const char* Qsrc = (const char*)g_Qh + ((size_t)(b * 32 + blockIdx.x)) * 65536;
    const uint32_t* Mw[4] = {
        reinterpret_cast<const uint32_t*>(mask_raw) + (size_t)(b * SS + q0 + R0) * SS,
        reinterpret_cast<const uint32_t*>(mask_raw) + (size_t)(b * SS + q0 + R1) * SS,
        reinterpret_cast<const uint32_t*>(mask_raw) + (size_t)(b * SS + q0 + R2) * SS,
        reinterpret_cast<const uint32_t*>(mask_raw) + (size_t)(b * SS + q0 + R3) * SS };
    const uint8_t* Mb[4] = {
        reinterpret_cast<const uint8_t*>(mask_raw) + (size_t)(b * SS + q0 + R0) * SS,
        reinterpret_cast<const uint8_t*>(mask_raw) + (size_t)(b * SS + q0 + R1) * SS,
        reinterpret_cast<const uint8_t*>(mask_raw) + (size_t)(b * SS + q0 + R2) * SS,
        reinterpret_cast<const uint8_t*>(mask_raw) + (size_t)(b * SS + q0 + R3) * SS };

    // ---- inline mask layout detection ----
    int bad = 0;
    {
        uint32_t w = reinterpret_cast<const uint32_t*>(mask_raw)[tid];
        bad = (w != 0u && w != 1u && w != 0x3F800000u) ? 1 : 0;
    }
    const int layout = __syncthreads_or(bad);   // 1 = packed bytes, 0 = word per element

    if (tid == 0) {
        MBAR_INIT(bm + 0, 1);
        MBAR_INIT(bm + 8, 1);
        MBAR_INIT(bm + 16, 1);
        MBAR_INIT(bm + 24, 256);
        MBAR_INIT(bm + 32, 256);
    }
    __syncthreads();
    if (tid == 0) {
        MBAR_EXPECT(bm + 16, 65536u);
        bulk_g2s(QB, Qsrc, 65536u, bm + 16);
        MBAR_EXPECT(bm + 0, 65536u);
        bulk_g2s(sb + K_OFF, Ksrc, 32768u, bm + 0);
        bulk_g2s(sb + V_OFF, Vsrc, 32768u, bm + 0);
        MBAR_EXPECT(bm + 8, 65536u);
        bulk_g2s(sb + K_OFF + 32768, Ksrc + 32768, 32768u, bm + 8);
        bulk_g2s(sb + V_OFF + 32768, Vsrc + 32768, 32768u, bm + 8);
    }

    auto load_mask_bits = [&](int t) -> uint32_t {
        uint32_t bits = 0;
        const int colb = t * 64 + h * 32 + 2 * lx;
        if (layout == 0) {
            #pragma unroll
            for (int nn = 0; nn < 4; nn++)
                #pragma unroll
                for (int f = 0; f < 4; f++) {
                    uint2 v = ldcs2(Mw[f] + colb + nn * 8);
                    if (v.x) bits |= 1u << (nn * 8 + f * 2);
                    if (v.y) bits |= 1u << (nn * 8 + f * 2 + 1);
                }
        } else {
            #pragma unroll
            for (int nn = 0; nn < 4; nn++)
                #pragma unroll
                for (int f = 0; f < 4; f++) {
                    uint32_t v = *reinterpret_cast<const uint16_t*>(Mb[f] + colb + nn * 8);
                    if (v & 0x00ffu) bits |= 1u << (nn * 8 + f * 2);
                    if (v & 0xff00u) bits |= 1u << (nn * 8 + f * 2 + 1);
                }
        }
        return bits;
    };

    float C[32][4];
    #pragma unroll
    for (int n = 0; n < 32; n++)
        #pragma unroll
        for (int j = 0; j < 4; j++) C[n][j] = 0.0f;
    float l[4] = {0.0f, 0.0f, 0.0f, 0.0f};

    const int rowA0 = rs + (lane & 15);
    const int rowA1 = rowA0 + 16;
    const int ra7   = rowA0 & 7;
    const uint32_t qrow0 = QB + rowA0 * 512;
    const uint32_t qrow1 = QB + rowA1 * 512;
    const uint32_t prow0 = PB + rowA0 * 128;
    const uint32_t prow1 = PB + rowA1 * 128;

    uint32_t mbits = load_mask_bits(0);
    MBAR_WAIT(bm + 16, 0);   // Q resident

    for (int t = 0; t < NT; t++) {
        const int buf = t & 1;
        const int ph  = (t >> 1) & 1;
        MBAR_WAIT(bm + buf * 8, ph);

        const uint32_t KBc = sb + K_OFF + buf * 32768;
        const uint32_t VBc = sb + V_OFF + buf * 32768;

        float S[8][4];
        #pragma unroll
        for (int n = 0; n < 8; n++)
            #pragma unroll
            for (int j = 0; j < 4; j++) S[n][j] = 0.0f;

        #pragma unroll
        for (int kk = 0; kk < 16; kk++) {
            uint32_t a0, a1, a2, a3, a4, a5, a6, a7;
            ldsm_x4(a0, a1, a2, a3, qrow0 + ((2 * kk + (lane >> 4)) ^ ra7) * 16);
            ldsm_x4(a4, a5, a6, a7, qrow1 + ((2 * kk + (lane >> 4)) ^ ra7) * 16);
            #pragma unroll
            for (int nn = 0; nn < 4; nn += 2) {
                int key = h * 32 + nn * 8 + ((lane >> 4) & 1) * 8 + (lane & 7);
                uint32_t b0, b1, b2, b3;
                ldsm_x4(b0, b1, b2, b3,
                        KBc + key * 512 + ((2 * kk + ((lane >> 3) & 1)) ^ (lane & 7)) * 16);
                mma16(S[nn * 2 + 0],       a0, a1, a2, a3, b0, b1);
                mma16(S[nn * 2 + 1],       a4, a5, a6, a7, b0, b1);
                mma16(S[(nn + 1) * 2 + 0], a0, a1, a2, a3, b2, b3);
                mma16(S[(nn + 1) * 2 + 1], a4, a5, a6, a7, b2, b3);
            }
        }

        uint32_t pp[4][4];
        #pragma unroll
        for (int nn = 0; nn < 4; nn++)
            #pragma unroll
            for (int m = 0; m < 2; m++) {
                float e0 = ex2f(S[nn * 2 + m][0] * EXP_C);
                float e1 = ex2f(S[nn * 2 + m][1] * EXP_C);
                float e2 = ex2f(S[nn * 2 + m][2] * EXP_C);
                float e3 = ex2f(S[nn * 2 + m][3] * EXP_C);
                e0 = (mbits >> (nn * 8 + (2 * m) * 2))     & 1u ? 0.0f : e0;
                e1 = (mbits >> (nn * 8 + (2 * m) * 2 + 1)) & 1u ? 0.0f : e1;
                e2 = (mbits >> (nn * 8 + (2 * m + 1) * 2))     & 1u ? 0.0f : e2;
                e3 = (mbits >> (nn * 8 + (2 * m + 1) * 2 + 1)) & 1u ? 0.0f : e3;
                l[2 * m]     += e0 + e1;
                l[2 * m + 1] += e2 + e3;
                pp[nn][2 * m]     = pack2(e0, e1);
                pp[nn][2 * m + 1] = pack2(e2, e3);
                const int cc = (h * 32 + nn * 8) >> 3;
                const int rA = rs + m * 16 + ly, rB = rA + 8;
                *reinterpret_cast<uint32_t*>(sm + P_OFF + rA * 128 + ((cc ^ (rA & 7)) * 16 + 4 * lx)) = pp[nn][2 * m];
                *reinterpret_cast<uint32_t*>(sm + P_OFF + rB * 128 + ((cc ^ (rB & 7)) * 16 + 4 * lx)) = pp[nn][2 * m + 1];
            }

        if (t + 1 < NT) mbits = load_mask_bits(t + 1);

        #pragma unroll
        for (int j = 0; j < 2; j++) {
            const int kc = 2 * h + j;
            const int key = kc * 16 + (lane & 7) + ((lane >> 3) & 1) * 8;
            const uint32_t vrow = VBc + key * 512;
            const int k7 = key & 7;
            uint32_t a00 = pp[2 * j][0],     a01 = pp[2 * j][1],     a02 = pp[2 * j + 1][0], a03 = pp[2 * j + 1][1];
            uint32_t a10 = pp[2 * j][2],     a11 = pp[2 * j][3],     a12 = pp[2 * j + 1][2], a13 = pp[2 * j + 1][3];
            #pragma unroll
            for (int nn = 0; nn < 16; nn += 2) {
                uint32_t b0, b1, b2, b3;
                ldsm_x4t(b0, b1, b2, b3, vrow + ((h * 16 + nn + ((lane >> 4) & 1)) ^ k7) * 16);
                mma16(C[nn * 2 + 0],       a00, a01, a02, a03, b0, b1);
                mma16(C[nn * 2 + 1],       a10, a11, a12, a13, b0, b1);
                mma16(C[(nn + 1) * 2 + 0], a00, a01, a02, a03, b2, b3);
                mma16(C[(nn + 1) * 2 + 1], a10, a11, a12, a13, b2, b3);
            }
        }

        PAIR_BAR(slab + 1);

        #pragma unroll
        for (int j = 0; j < 2; j++) {
            const int kc = 2 * (1 - h) + j;
            const int key = kc * 16 + (lane & 7) + ((lane >> 3) & 1) * 8;
            const uint32_t vrow = VBc + key * 512;
            const int k7 = key & 7;
            uint32_t a00, a01, a02, a03, a10, a11, a12, a13;
            ldsm_x4(a00, a01, a02, a03, prow0 + ((2 * kc + (lane >> 4)) ^ ra7) * 16);
            ldsm_x4(a10, a11, a12, a13, prow1 + ((2 * kc + (lane >> 4)) ^ ra7) * 16);
            #pragma unroll
            for (int nn = 0; nn < 16; nn += 2) {
                uint32_t b0, b1, b2, b3;
                ldsm_x4t(b0, b1, b2, b3, vrow + ((h * 16 + nn + ((lane >> 4) & 1)) ^ k7) * 16);
                mma16(C[nn * 2 + 0],       a00, a01, a02, a03, b0, b1);
                mma16(C[nn * 2 + 1],       a10, a11, a12, a13, b0, b1);
                mma16(C[(nn + 1) * 2 + 0], a00, a01, a02, a03, b2, b3);
                mma16(C[(nn + 1) * 2 + 1], a10, a11, a12, a13, b2, b3);
            }
        }

        PAIR_BAR(slab + 1);

        MBAR_ARRIVE(bm + 24 + buf * 8);

        if (tid == 0 && t + 2 < NT) {
            MBAR_WAIT(bm + 24 + buf * 8, ph);
            const uint32_t db = bm + buf * 8;
            MBAR_EXPECT(db, 65536u);
            bulk_g2s(sb + K_OFF + buf * 32768, Ksrc + (size_t)(t + 2) * 32768, 32768u, db);
            bulk_g2s(sb + V_OFF + buf * 32768, Vsrc + (size_t)(t + 2) * 32768, 32768u, db);
        }
    }

    // ---- epilogue ----
    #pragma unroll
    for (int f = 0; f < 4; f++) {
        l[f] += __shfl_xor_sync(0xffffffffu, l[f], 1);
        l[f] += __shfl_xor_sync(0xffffffffu, l[f], 2);
    }
    if (lx == 0) {
        lred[R0 * 2 + h] = l[0];
        lred[R1 * 2 + h] = l[1];
        lred[R2 * 2 + h] = l[2];
        lred[R3 * 2 + h] = l[3];
    }
    __syncthreads();
    float inv[4];
    inv[0] = 1.0f / (lred[R0 * 2] + lred[R0 * 2 + 1]);
    inv[1] = 1.0f / (lred[R1 * 2] + lred[R1 * 2 + 1]);
    inv[2] = 1.0f / (lred[R2 * 2] + lred[R2 * 2 + 1]);
    inv[3] = 1.0f / (lred[R3 * 2] + lred[R3 * 2 + 1]);

    #pragma unroll
    for (int nn = 0; nn < 16; nn++)
        #pragma unroll
        for (int m = 0; m < 2; m++) {
            const int col = h * 128 + nn * 8 + 2 * lx;
            const int rA = rs + m * 16 + ly, rB = rA + 8;
            float2 o0 = { C[nn * 2 + m][0] * inv[2 * m],     C[nn * 2 + m][1] * inv[2 * m] };
            float2 o1 = { C[nn * 2 + m][2] * inv[2 * m + 1], C[nn * 2 + m][3] * inv[2 * m + 1] };
            *reinterpret_cast<float2*>(out + (size_t)(b * SS + q0 + rA) * DD + col) = o0;
            *reinterpret_cast<float2*>(out + (size_t)(b * SS + q0 + rB) * DD + col) = o1;
        }
}

// ---------------------------------------------------------------------------
extern "C" void kernel_launch(void* const* d_in, const int* in_sizes, int n_in,
                              void* d_out, int out_size)
{
    const float*    X    = (const float*)d_in[0];
    const uint32_t* mask = (const uint32_t*)d_in[1];
    const float*    Wq   = (const float*)d_in[2];
    const float*    bq   = (const float*)d_in[3];
    const float*    Wk   = (const float*)d_in[4];
    const float*    bk   = (const float*)d_in[5];
    const float*    Wv   = (const float*)d_in[6];
    const float*    bv   = (const float*)d_in[7];
    float*          out  = (float*)d_out;

    convert_kernel<<<2144, 256>>>(X, Wq, Wk, Wv);

    const int proj_smem = 196608 + 16;      // Xs 64K + Ws 128K + mbars
    cudaFuncSetAttribute(proj_mma_kernel, cudaFuncAttributeMaxDynamicSharedMemorySize, proj_smem);
    proj_mma_kernel<<<128, 512, proj_smem>>>(bq, bk, bv);

    const int attn_smem = 214016 + 64;
    cudaFuncSetAttribute(attn_mma_kernel, cudaFuncAttributeMaxDynamicSharedMemorySize, attn_smem);
    attn_mma_kernel<<<dim3(SS / 128, BB), 256, attn_smem>>>(out, (const void*)mask);
}